// round 16
// baseline (speedup 1.0000x reference)
#include <cuda_runtime.h>
#include <cstdint>

// BallPointQuery: per centroid, indices of up to 64 points within RADIUS
// (ascending), padded with first-neighbor index (0 if none).
// B=8, N=16384, M=1024, K=64. Output dtype: FLOAT32 (indices as floats).
//
// Round 16: move the prefetch buffer from registers to smem via cp.async.
// R13/R15's register ping-pong (80 regs) capped residency at 6 blocks/SM;
// per-lane cp.async staging frees ~24 regs -> 8 blocks/SM (32 warps) while
// keeping 1-deep async prefetch. Each lane stages/reads ONLY its own 96B
// region (112B padded, LDS.128 conflict-free) -> no barriers; per-thread
// cp.async group ordering is sufficient (in-order completion makes stale
// prefetches from early-exited centroids harmless).
// Kept: f32x2 packed math, bit-sliced ballot prefix, sparse ffs writes,
// warp work stealing, eps-band +-1e-5 around r2=0.04 + exact expanded-
// formula fallback => rel_err must remain exactly 4.700719e-4.

#define BB 8
#define NN 16384
#define MM 1024
#define KSAMP 64
#define TOTAL_WARPS (BB * MM)

#define LANE_BYTES   112              // 96B data + 16B pad (bank spread)
#define STAGE_BYTES  (32 * LANE_BYTES)   // 3584
#define WARP_BYTES   (2 * STAGE_BYTES)   // 7168
#define BLOCK_WARPS  4
#define SMEM_BYTES   (BLOCK_WARPS * WARP_BYTES)  // 28672

typedef unsigned long long ull;

#define ADDX2(out, a, b) \
    asm("add.rn.f32x2 %0, %1, %2;" : "=l"(out) : "l"(a), "l"(b))
#define MULX2(out, a, b) \
    asm("mul.rn.f32x2 %0, %1, %2;" : "=l"(out) : "l"(a), "l"(b))
#define FMAX2(out, a, b, c) \
    asm("fma.rn.f32x2 %0, %1, %2, %3;" : "=l"(out) : "l"(a), "l"(b), "l"(c))

#define CP16(dst_u32, src_ptr) \
    asm volatile("cp.async.ca.shared.global [%0], [%1], 16;" \
                 :: "r"(dst_u32), "l"(src_ptr))
#define CP_COMMIT() asm volatile("cp.async.commit_group;")
#define CP_WAIT1()  asm volatile("cp.async.wait_group 1;")
#define CP_WAIT0()  asm volatile("cp.async.wait_group 0;")

__device__ unsigned g_ctr;

__global__ void reset_ctr_kernel() { g_ctr = 0u; }

__device__ __forceinline__ float lo_f(ull v) {
    return __uint_as_float((unsigned)v);
}
__device__ __forceinline__ float hi_f(ull v) {
    return __uint_as_float((unsigned)(v >> 32));
}

__device__ __forceinline__ float exact_d2(float c2, float cx, float cy, float cz,
                                          float x, float y, float z)
{
    float p2 = __fadd_rn(__fadd_rn(__fmul_rn(x, x), __fmul_rn(y, y)),
                         __fmul_rn(z, z));
    float cp = __fadd_rn(__fadd_rn(__fmul_rn(cx, x), __fmul_rn(cy, y)),
                         __fmul_rn(cz, z));
    return __fsub_rn(__fadd_rn(c2, p2), __fmul_rn(2.0f, cp));
}

__global__ void __launch_bounds__(128, 8)
ballquery_kernel(const float* __restrict__ pts,    // [8, 3, 16384]
                 const float* __restrict__ cent,   // [8, 3, 1024]
                 float* __restrict__ out)          // [8, 1024, 64] f32
{
    __shared__ __align__(16) char sbuf[SMEM_BYTES];

    const unsigned FULL = 0xffffffffu;
    int lane = (int)(threadIdx.x & 31);
    int winb = (int)(threadIdx.x >> 5);

    // This lane's private staging region (u32 shared address for cp.async,
    // generic pointer for LDS reads).
    char* lane_buf = sbuf + winb * WARP_BYTES + lane * LANE_BYTES;
    unsigned lane_su32 = (unsigned)__cvta_generic_to_shared(lane_buf);

    const float r2   = 0.04f;
    const float R2LO = 0.04f - 1e-5f;
    const float R2HI = 0.04f + 1e-5f;
    const unsigned below = (1u << lane) - 1u;
    const int nl = 8 * lane;

    for (;;) {
        unsigned widx;
        if (lane == 0) widx = atomicAdd(&g_ctr, 1u);
        widx = __shfl_sync(FULL, widx, 0);
        if (widx >= TOTAL_WARPS) { CP_WAIT0(); return; }

        int b = (int)(widx >> 10);
        int m = (int)(widx & (MM - 1));

        const float* px = pts + (size_t)b * 3 * NN;   // y at +NN, z at +2*NN
        const float* cb = cent + (size_t)b * 3 * MM;

        float cx = __ldg(cb + m);
        float cy = __ldg(cb + MM + m);
        float cz = __ldg(cb + 2 * MM + m);

        float c2 = __fadd_rn(__fadd_rn(__fmul_rn(cx, cx), __fmul_rn(cy, cy)),
                             __fmul_rn(cz, cz));

        ull ncx2, ncy2, ncz2;   // packed (-c, -c)
        {
            unsigned nx = __float_as_uint(-cx);
            unsigned ny = __float_as_uint(-cy);
            unsigned nz = __float_as_uint(-cz);
            ncx2 = ((ull)nx << 32) | nx;
            ncy2 = ((ull)ny << 32) | ny;
            ncz2 = ((ull)nz << 32) | nz;
        }

        float* __restrict__ row = out + (size_t)widx * KSAMP;

        int base = 0;
        int first_idx = -1;
        int stage = 0;

        // Prologue: stage chunk 0.
        {
            const float* g = px + nl;
            unsigned d = lane_su32;                 // stage 0
            CP16(d +  0, g);          CP16(d + 16, g + 4);
            CP16(d + 32, g + NN);     CP16(d + 48, g + NN + 4);
            CP16(d + 64, g + 2 * NN); CP16(d + 80, g + 2 * NN + 4);
            CP_COMMIT();
        }

        for (int n0 = 0; n0 < NN; n0 += 256) {
            bool more = (n0 + 256) < NN;
            if (more) {
                const float* g = px + n0 + 256 + nl;
                unsigned d = lane_su32 + (stage ^ 1) * STAGE_BYTES;
                CP16(d +  0, g);          CP16(d + 16, g + 4);
                CP16(d + 32, g + NN);     CP16(d + 48, g + NN + 4);
                CP16(d + 64, g + 2 * NN); CP16(d + 80, g + 2 * NN + 4);
                CP_COMMIT();
                CP_WAIT1();   // current stage's group (and older) complete
            } else {
                CP_WAIT0();
            }

            const double2* sp =
                (const double2*)(lane_buf + stage * STAGE_BYTES);
            ull Xp[4], Yp[4], Zp[4];
            {
                double2 v;
                v = sp[0]; Xp[0] = __double_as_longlong(v.x); Xp[1] = __double_as_longlong(v.y);
                v = sp[1]; Xp[2] = __double_as_longlong(v.x); Xp[3] = __double_as_longlong(v.y);
                v = sp[2]; Yp[0] = __double_as_longlong(v.x); Yp[1] = __double_as_longlong(v.y);
                v = sp[3]; Yp[2] = __double_as_longlong(v.x); Yp[3] = __double_as_longlong(v.y);
                v = sp[4]; Zp[0] = __double_as_longlong(v.x); Zp[1] = __double_as_longlong(v.y);
                v = sp[5]; Zp[2] = __double_as_longlong(v.x); Zp[3] = __double_as_longlong(v.y);
            }

            unsigned h = 0, band = 0;
            #pragma unroll
            for (int p = 0; p < 4; p++) {
                ull dx, dy, dz, s;
                ADDX2(dx, Xp[p], ncx2);
                ADDX2(dy, Yp[p], ncy2);
                ADDX2(dz, Zp[p], ncz2);
                MULX2(s, dx, dx);
                FMAX2(s, dy, dy, s);
                FMAX2(s, dz, dz, s);
                float d0 = lo_f(s), d1 = hi_f(s);
                if (d0 <= R2HI) { if (d0 <= R2LO) h |= 1u << (2*p);   else band |= 1u << (2*p); }
                if (d1 <= R2HI) { if (d1 <= R2LO) h |= 1u << (2*p+1); else band |= 1u << (2*p+1); }
            }

            // Rare borderline points: exact expanded formula decides.
            if (__ballot_sync(FULL, band != 0u)) {
                #pragma unroll
                for (int j = 0; j < 8; j++) {
                    if (band & (1u << j)) {
                        float x = (j & 1) ? hi_f(Xp[j >> 1]) : lo_f(Xp[j >> 1]);
                        float y = (j & 1) ? hi_f(Yp[j >> 1]) : lo_f(Yp[j >> 1]);
                        float z = (j & 1) ? hi_f(Zp[j >> 1]) : lo_f(Zp[j >> 1]);
                        if (exact_d2(c2, cx, cy, cz, x, y, z) <= r2)
                            h |= (1u << j);
                    }
                }
            }

            stage ^= 1;

            unsigned hb = __ballot_sync(FULL, h != 0u);
            if (!hb) continue;                  // warp-uniform: empty chunk

            if (first_idx < 0) {
                int l0 = __ffs(hb) - 1;
                unsigned h0 = __shfl_sync(FULL, h, l0);
                first_idx = n0 + 8 * l0 + (__ffs(h0) - 1);
            }

            // Bit-sliced ballot prefix over per-lane counts (0..8).
            int cnt = __popc(h);
            unsigned q0 = __ballot_sync(FULL, cnt & 1);
            unsigned q1 = __ballot_sync(FULL, cnt & 2);
            unsigned q2 = __ballot_sync(FULL, cnt & 4);
            unsigned q3 = __ballot_sync(FULL, cnt & 8);
            int myPos = base
                      + __popc(q0 & below)
                      + 2 * __popc(q1 & below)
                      + 4 * __popc(q2 & below)
                      + 8 * __popc(q3 & below);
            int total = __popc(q0) + 2 * __popc(q1)
                      + 4 * __popc(q2) + 8 * __popc(q3);

            // Sparse write: one iteration per actual hit in this lane.
            int base_n = n0 + nl;
            unsigned hh = h;
            while (hh) {
                int j = __ffs(hh) - 1;
                hh &= hh - 1;
                if (myPos < KSAMP)
                    row[myPos] = (float)(base_n + j);
                myPos++;
            }
            base += total;
            if (base >= KSAMP) break;           // warp-uniform
        }

        int cnt = base < KSAMP ? base : KSAMP;
        if (first_idx < 0) first_idx = 0;
        float pad = (float)first_idx;
        for (int s = cnt + lane; s < KSAMP; s += 32)
            row[s] = pad;
    }
}

extern "C" void kernel_launch(void* const* d_in, const int* in_sizes, int n_in,
                              void* d_out, int out_size)
{
    // points = largest input, centroids = smallest (robust binding).
    int ip = 0, ic = 0;
    for (int i = 1; i < n_in; i++) {
        if (in_sizes[i] > in_sizes[ip]) ip = i;
        if (in_sizes[i] < in_sizes[ic]) ic = i;
    }
    if (ip == ic && n_in >= 2) { ip = 0; ic = 1; }

    const float* pts  = (const float*)d_in[ip];
    const float* cent = (const float*)d_in[ic];
    float* out = (float*)d_out;

    reset_ctr_kernel<<<1, 1>>>();

    // Resident-sized persistent grid: 8 blocks/SM (28KB smem, <=64 regs)
    // x 148 SMs = 1184 blocks, 4736 warps stealing 8192 centroids.
    const int threads = 128;
    const int blocks  = 1184;
    ballquery_kernel<<<blocks, threads>>>(pts, cent, out);
}

// round 17
// speedup vs baseline: 1.1623x; 1.1623x over previous
#include <cuda_runtime.h>
#include <cstdint>

// BallPointQuery: per centroid, indices of up to 64 points within RADIUS
// (ascending), padded with first-neighbor index (0 if none).
// B=8, N=16384, M=1024, K=64. Output dtype: FLOAT32 (indices as floats).
//
// Round 17 (= R15 scan kernel + hard-first scheduling):
//  R16's cp.async smem staging regressed (reverted). The remaining loss is
//  the long-scan TAIL: corner-region centroids (clipped ball -> expected
//  hits < 64) scan all 64 chunks (7x mean). A classify pre-kernel orders
//  centroids hard-first (lambda_est < 128 via per-axis spherical-cap
//  clipping) so long scans start early; work stealing absorbs the rest.
//  Scan kernel identical to R15: 256-pt chunks, register ping-pong
//  prefetch, f32x2 packed math on double2 pairs, bit-sliced ballot prefix,
//  sparse ffs writes, eps-band +-1e-5 + exact expanded-formula fallback.
//  => per-centroid results unchanged: rel_err must stay 4.700719e-4.

#define BB 8
#define NN 16384
#define MM 1024
#define KSAMP 64
#define TOTAL_WARPS (BB * MM)

typedef unsigned long long ull;

#define ADDX2(out, a, b) \
    asm("add.rn.f32x2 %0, %1, %2;" : "=l"(out) : "l"(a), "l"(b))
#define MULX2(out, a, b) \
    asm("mul.rn.f32x2 %0, %1, %2;" : "=l"(out) : "l"(a), "l"(b))
#define FMAX2(out, a, b, c) \
    asm("fma.rn.f32x2 %0, %1, %2, %3;" : "=l"(out) : "l"(a), "l"(b), "l"(c))

__device__ unsigned g_ctr;        // steal counter (scan kernel)
__device__ unsigned g_hard;       // hard-bucket append counter
__device__ unsigned g_easy;       // easy-bucket append counter
__device__ unsigned short g_order[TOTAL_WARPS];

__global__ void reset_ctr_kernel() { g_ctr = 0u; g_hard = 0u; g_easy = 0u; }

// Classify centroids: estimated in-ball point count via per-axis spherical
// cap clipping. lambda_est < 128 => "hard" (long scan) => front of queue.
__global__ void classify_kernel(const float* __restrict__ cent)
{
    int widx = blockIdx.x * blockDim.x + threadIdx.x;
    if (widx >= TOTAL_WARPS) return;
    int b = widx >> 10;
    int m = widx & (MM - 1);
    const float* cb = cent + (size_t)b * 3 * MM;
    float c[3] = { cb[m], cb[MM + m], cb[2 * MM + m] };

    const float r = 0.2f;
    float frac = 1.0f;
    #pragma unroll
    for (int d = 0; d < 3; d++) {
        float t = fminf(c[d], 1.0f - c[d]);      // distance to nearest face
        if (t < r) {
            float hcap = r - t;                   // cap height
            // cap volume fraction of ball: h^2(3r-h) / (4 r^3)
            float fcap = hcap * hcap * (3.0f * r - hcap) / (4.0f * r * r * r);
            frac *= (1.0f - fcap);
        }
    }
    float lam = 549.0f * frac;   // N * V_ball = 16384 * 0.0335

    if (lam < 128.0f) {
        unsigned p = atomicAdd(&g_hard, 1u);
        g_order[p] = (unsigned short)widx;
    } else {
        unsigned p = atomicAdd(&g_easy, 1u);
        g_order[TOTAL_WARPS - 1 - p] = (unsigned short)widx;
    }
}

__device__ __forceinline__ float lo_f(ull v) {
    return __uint_as_float((unsigned)v);
}
__device__ __forceinline__ float hi_f(ull v) {
    return __uint_as_float((unsigned)(v >> 32));
}

__device__ __forceinline__ float exact_d2(float c2, float cx, float cy, float cz,
                                          float x, float y, float z)
{
    float p2 = __fadd_rn(__fadd_rn(__fmul_rn(x, x), __fmul_rn(y, y)),
                         __fmul_rn(z, z));
    float cp = __fadd_rn(__fadd_rn(__fmul_rn(cx, x), __fmul_rn(cy, y)),
                         __fmul_rn(cz, z));
    return __fsub_rn(__fadd_rn(c2, p2), __fmul_rn(2.0f, cp));
}

__global__ void __launch_bounds__(128)
ballquery_kernel(const float* __restrict__ pts,    // [8, 3, 16384]
                 const float* __restrict__ cent,   // [8, 3, 1024]
                 float* __restrict__ out)          // [8, 1024, 64] f32
{
    const unsigned FULL = 0xffffffffu;
    int lane = (int)(threadIdx.x & 31);

    const float r2   = 0.04f;
    const float R2LO = 0.04f - 1e-5f;
    const float R2HI = 0.04f + 1e-5f;
    const unsigned below = (1u << lane) - 1u;

    for (;;) {
        unsigned slot;
        if (lane == 0) slot = atomicAdd(&g_ctr, 1u);
        slot = __shfl_sync(FULL, slot, 0);
        if (slot >= TOTAL_WARPS) return;
        unsigned widx = g_order[slot];     // hard-first order

        int b = (int)(widx >> 10);
        int m = (int)(widx & (MM - 1));

        const float* px = pts + (size_t)b * 3 * NN;   // y at +NN, z at +2*NN
        const float* cb = cent + (size_t)b * 3 * MM;

        float cx = __ldg(cb + m);
        float cy = __ldg(cb + MM + m);
        float cz = __ldg(cb + 2 * MM + m);

        float c2 = __fadd_rn(__fadd_rn(__fmul_rn(cx, cx), __fmul_rn(cy, cy)),
                             __fmul_rn(cz, cz));

        ull ncx2, ncy2, ncz2;   // packed (-c, -c)
        {
            unsigned nx = __float_as_uint(-cx);
            unsigned ny = __float_as_uint(-cy);
            unsigned nz = __float_as_uint(-cz);
            ncx2 = ((ull)nx << 32) | nx;
            ncy2 = ((ull)ny << 32) | ny;
            ncz2 = ((ull)nz << 32) | nz;
        }

        float* __restrict__ row = out + (size_t)widx * KSAMP;

        int base = 0;
        int first_idx = -1;
        const int nl = 8 * lane;

        // Process one 256-point chunk; returns true when 64 hits reached.
        auto chunk = [&](int n0, double2 X0, double2 X1, double2 Y0,
                         double2 Y1, double2 Z0, double2 Z1) -> bool {
            ull Xp[4] = { __double_as_longlong(X0.x), __double_as_longlong(X0.y),
                          __double_as_longlong(X1.x), __double_as_longlong(X1.y) };
            ull Yp[4] = { __double_as_longlong(Y0.x), __double_as_longlong(Y0.y),
                          __double_as_longlong(Y1.x), __double_as_longlong(Y1.y) };
            ull Zp[4] = { __double_as_longlong(Z0.x), __double_as_longlong(Z0.y),
                          __double_as_longlong(Z1.x), __double_as_longlong(Z1.y) };

            unsigned h = 0, band = 0;
            #pragma unroll
            for (int p = 0; p < 4; p++) {
                ull dx, dy, dz, s;
                ADDX2(dx, Xp[p], ncx2);
                ADDX2(dy, Yp[p], ncy2);
                ADDX2(dz, Zp[p], ncz2);
                MULX2(s, dx, dx);
                FMAX2(s, dy, dy, s);
                FMAX2(s, dz, dz, s);
                float d0 = lo_f(s), d1 = hi_f(s);
                if (d0 <= R2HI) { if (d0 <= R2LO) h |= 1u << (2*p);   else band |= 1u << (2*p); }
                if (d1 <= R2HI) { if (d1 <= R2LO) h |= 1u << (2*p+1); else band |= 1u << (2*p+1); }
            }

            // Rare borderline points: exact expanded formula decides.
            if (__ballot_sync(FULL, band != 0u)) {
                #pragma unroll
                for (int j = 0; j < 8; j++) {
                    if (band & (1u << j)) {
                        float x = (j & 1) ? hi_f(Xp[j >> 1]) : lo_f(Xp[j >> 1]);
                        float y = (j & 1) ? hi_f(Yp[j >> 1]) : lo_f(Yp[j >> 1]);
                        float z = (j & 1) ? hi_f(Zp[j >> 1]) : lo_f(Zp[j >> 1]);
                        if (exact_d2(c2, cx, cy, cz, x, y, z) <= r2)
                            h |= (1u << j);
                    }
                }
            }

            unsigned hb = __ballot_sync(FULL, h != 0u);
            if (!hb) return false;              // warp-uniform: empty chunk

            if (first_idx < 0) {
                int l0 = __ffs(hb) - 1;
                unsigned h0 = __shfl_sync(FULL, h, l0);
                first_idx = n0 + 8 * l0 + (__ffs(h0) - 1);
            }

            // Bit-sliced ballot prefix over per-lane counts (0..8).
            int cnt = __popc(h);
            unsigned q0 = __ballot_sync(FULL, cnt & 1);
            unsigned q1 = __ballot_sync(FULL, cnt & 2);
            unsigned q2 = __ballot_sync(FULL, cnt & 4);
            unsigned q3 = __ballot_sync(FULL, cnt & 8);
            int myPos = base
                      + __popc(q0 & below)
                      + 2 * __popc(q1 & below)
                      + 4 * __popc(q2 & below)
                      + 8 * __popc(q3 & below);
            int total = __popc(q0) + 2 * __popc(q1)
                      + 4 * __popc(q2) + 8 * __popc(q3);

            // Sparse write: one iteration per actual hit in this lane.
            int base_n = n0 + nl;
            unsigned hh = h;
            while (hh) {
                int j = __ffs(hh) - 1;
                hh &= hh - 1;
                if (myPos < KSAMP)
                    row[myPos] = (float)(base_n + j);
                myPos++;
            }
            base += total;
            return base >= KSAMP;               // warp-uniform
        };

        // Ping-pong double-buffered scan (64 chunks; even count).
        double2 AX0 = __ldg((const double2*)(px + nl));
        double2 AX1 = __ldg((const double2*)(px + nl + 4));
        double2 AY0 = __ldg((const double2*)(px + NN + nl));
        double2 AY1 = __ldg((const double2*)(px + NN + nl + 4));
        double2 AZ0 = __ldg((const double2*)(px + 2 * NN + nl));
        double2 AZ1 = __ldg((const double2*)(px + 2 * NN + nl + 4));
        double2 BX0, BX1, BY0, BY1, BZ0, BZ1;

        for (int n0 = 0;;) {
            bool more = (n0 + 256) < NN;
            if (more) {
                int nn = n0 + 256 + nl;
                BX0 = __ldg((const double2*)(px + nn));
                BX1 = __ldg((const double2*)(px + nn + 4));
                BY0 = __ldg((const double2*)(px + NN + nn));
                BY1 = __ldg((const double2*)(px + NN + nn + 4));
                BZ0 = __ldg((const double2*)(px + 2 * NN + nn));
                BZ1 = __ldg((const double2*)(px + 2 * NN + nn + 4));
            }
            if (chunk(n0, AX0, AX1, AY0, AY1, AZ0, AZ1) || !more) break;
            n0 += 256;

            bool more2 = (n0 + 256) < NN;
            if (more2) {
                int nn = n0 + 256 + nl;
                AX0 = __ldg((const double2*)(px + nn));
                AX1 = __ldg((const double2*)(px + nn + 4));
                AY0 = __ldg((const double2*)(px + NN + nn));
                AY1 = __ldg((const double2*)(px + NN + nn + 4));
                AZ0 = __ldg((const double2*)(px + 2 * NN + nn));
                AZ1 = __ldg((const double2*)(px + 2 * NN + nn + 4));
            }
            if (chunk(n0, BX0, BX1, BY0, BY1, BZ0, BZ1) || !more2) break;
            n0 += 256;
        }

        int cnt = base < KSAMP ? base : KSAMP;
        if (first_idx < 0) first_idx = 0;
        float pad = (float)first_idx;
        for (int s = cnt + lane; s < KSAMP; s += 32)
            row[s] = pad;
    }
}

extern "C" void kernel_launch(void* const* d_in, const int* in_sizes, int n_in,
                              void* d_out, int out_size)
{
    // points = largest input, centroids = smallest (robust binding).
    int ip = 0, ic = 0;
    for (int i = 1; i < n_in; i++) {
        if (in_sizes[i] > in_sizes[ip]) ip = i;
        if (in_sizes[i] < in_sizes[ic]) ic = i;
    }
    if (ip == ic && n_in >= 2) { ip = 0; ic = 1; }

    const float* pts  = (const float*)d_in[ip];
    const float* cent = (const float*)d_in[ic];
    float* out = (float*)d_out;

    reset_ctr_kernel<<<1, 1>>>();
    classify_kernel<<<(TOTAL_WARPS + 255) / 256, 256>>>(cent);

    // Resident-sized persistent grid: 6 blocks/SM @ 80 regs x 148 SMs.
    const int threads = 128;
    const int blocks  = 888;
    ballquery_kernel<<<blocks, threads>>>(pts, cent, out);
}